// round 14
// baseline (speedup 1.0000x reference)
#include <cuda_runtime.h>
#include <cstddef>

// KPN per-pixel dynamic convolution, K=15.
// data:    [1, 8, 3, 96, 96]      float32
// kernels: [1, 8, 225, 3, 96, 96] float32   (tap-major: k = i*15 + j)
// out:     [1, 8, 3, 96, 96]      float32
//
// R14 = R13 (balanced 113/112 z-split, 1 CTA/SM, pipelined prologue)
// + L2 software prefetch: while processing tap row i, lanes 0/8/16/24 of
// each warp prefetch.global.L2 the next row's 15 taps (1 req per 128B line,
// zero register/scoreboard cost). Next row's demand LDGs then hit L2
// (234cyc) instead of DRAM (577cyc); the prefetch engine drives the DRAM
// queue instead of the register file.

#define KSZ    15
#define PAD    7
#define HH     96
#define WW     96
#define CCH    3
#define TTT    8
#define TILE_H 16
#define SMEM_W 112                 // 96 + 14 halo = 110 -> 112 (16B align)
#define SMEM_H (TILE_H + KSZ - 1)  // 30
#define SLAB   (HH * WW)           // 9216
#define KSTRIDE (CCH * HH * WW)    // 27648 floats between consecutive taps
#define NTHREADS (24 * TILE_H * 2) // 768
#define TILE_N  (SMEM_H * SMEM_W)  // 3360
#define NLOAD   ((TILE_N + NTHREADS - 1) / NTHREADS)  // 5

#define PREFETCH_L2(p) asm volatile("prefetch.global.L2 [%0];" :: "l"(p))

__global__ __launch_bounds__(NTHREADS, 1)
void kpn_kernel(const float* __restrict__ data,
                const float* __restrict__ kernels,
                float* __restrict__ out)
{
    __shared__ float tile[TILE_N];                 // 13440 B
    __shared__ float part[TILE_H][24][4];          //  6144 B

    const int tc = blockIdx.y;             // t*3 + c, 0..23
    const int h0 = blockIdx.x * TILE_H;    // output row base
    const float* dslab = data + (size_t)tc * SLAB;

    const int tx = threadIdx.x;            // 0..23  (w / 4)
    const int ty = threadIdx.y;            // 0..15  (row in tile)
    const int tz = threadIdx.z;            // 0..1   (tap-row group)
    const int tid = (tz * TILE_H + ty) * 24 + tx;   // 0..767
    const bool pf_lane = ((tid & 7) == 0); // 4 lanes/warp prefetch (128B lines)

    const int w = tx * 4;                  // 0,4,...,92
    const int h = h0 + ty;
    const int t = tc / CCH;
    const int c = tc - t * CCH;

    // kernels[t, k, c, h, w] with k varying: base + k*KSTRIDE
    const float* kbase = kernels
        + ((size_t)(t * (KSZ * KSZ)) * CCH + c) * SLAB
        + (size_t)h * WW + w;

    const int i0 = tz * 8;                 // tz=0: rows 0..6(+7A); tz=1: rows 8..14(+7B)
    const float* kp0 = kbase + (size_t)(i0 * KSZ) * KSTRIDE;

    // ---- pipelined prologue ----
    // 1) tile gathers into registers (DRAM latency starts now)
    float tv[NLOAD];
    #pragma unroll
    for (int v = 0; v < NLOAD; v++) {
        const int idx = v * NTHREADS + tid;
        float val = 0.0f;
        if (idx < TILE_N) {
            const int r  = idx / SMEM_W;
            const int cc = idx - r * SMEM_W;
            const int gh = h0 - PAD + r;
            const int gw = cc - PAD;
            if ((unsigned)gh < (unsigned)HH && (unsigned)gw < (unsigned)WW)
                val = dslab[gh * WW + gw];
        }
        tv[v] = val;
    }
    // 2) first kv batch (independent of tile) — stream starts here
    float4 kv[8];
    #pragma unroll
    for (int u = 0; u < 8; u++)
        kv[u] = __ldcs(reinterpret_cast<const float4*>(
            kp0 + (size_t)u * KSTRIDE));
    // 2b) prefetch remainder of row i0 + all of row i0+1 into L2
    if (pf_lane) {
        #pragma unroll
        for (int u = 8; u < KSZ; u++)
            PREFETCH_L2(kp0 + (size_t)u * KSTRIDE);
        const float* kpn = kp0 + (size_t)KSZ * KSTRIDE;
        #pragma unroll
        for (int u = 0; u < KSZ; u++)
            PREFETCH_L2(kpn + (size_t)u * KSTRIDE);
    }
    // 3) tile stores + barrier (latency of 1+2 overlaps this wait)
    #pragma unroll
    for (int v = 0; v < NLOAD; v++) {
        const int idx = v * NTHREADS + tid;
        if (idx < TILE_N) tile[idx] = tv[v];
    }
    __syncthreads();

    float acc0 = 0.0f, acc1 = 0.0f, acc2 = 0.0f, acc3 = 0.0f;

    // ---- 7 full tap rows per z-half ----
    #pragma unroll
    for (int ii = 0; ii < 7; ii++) {
        const int i = i0 + ii;                   // tap row

        // data row segment: smem cols w .. w+19 (taps j=0..14 for 4 outputs)
        const float* row = &tile[(ty + i) * SMEM_W + w];
        float d[20];
        #pragma unroll
        for (int v4 = 0; v4 < 5; v4++) {
            const float4 rv = *reinterpret_cast<const float4*>(row + v4 * 4);
            d[v4 * 4 + 0] = rv.x;
            d[v4 * 4 + 1] = rv.y;
            d[v4 * 4 + 2] = rv.z;
            d[v4 * 4 + 3] = rv.w;
        }
        const float* kp = kbase + (size_t)(i * KSZ) * KSTRIDE;

        // batch A: taps 0..7 (prefetched to regs for ii==0)
        if (ii != 0) {
            #pragma unroll
            for (int u = 0; u < 8; u++)
                kv[u] = __ldcs(reinterpret_cast<const float4*>(
                    kp + (size_t)u * KSTRIDE));
        }
        // L2 prefetch of the row after next (rows i0+2 .. i0+7, and for
        // ii==5/6 the shared row 7 region gets covered by ii==5's i+2=
        // (i0+7): for tz=0 that IS row 7; for tz=1 i0+... row 15 doesn't
        // exist, so clamp to row 7 (its half B is what tz=1 needs).
        {
            int ipf = i + 2;
            if (ipf > i0 + 7) ipf = 7;       // tz=1 wraps to shared row 7
            if (ii < 7 && pf_lane) {
                const float* kpn = kbase + (size_t)(ipf * KSZ) * KSTRIDE;
                #pragma unroll
                for (int u = 0; u < KSZ; u++)
                    PREFETCH_L2(kpn + (size_t)u * KSTRIDE);
            }
        }
        #pragma unroll
        for (int u = 0; u < 8; u++) {
            acc0 = fmaf(kv[u].x, d[u + 0], acc0);
            acc1 = fmaf(kv[u].y, d[u + 1], acc1);
            acc2 = fmaf(kv[u].z, d[u + 2], acc2);
            acc3 = fmaf(kv[u].w, d[u + 3], acc3);
        }
        // batch B: taps 8..14
        {
            float4 kb[7];
            #pragma unroll
            for (int u = 0; u < 7; u++)
                kb[u] = __ldcs(reinterpret_cast<const float4*>(
                    kp + (size_t)(8 + u) * KSTRIDE));
            #pragma unroll
            for (int u = 0; u < 7; u++) {
                const int j = 8 + u;
                acc0 = fmaf(kb[u].x, d[j + 0], acc0);
                acc1 = fmaf(kb[u].y, d[j + 1], acc1);
                acc2 = fmaf(kb[u].z, d[j + 2], acc2);
                acc3 = fmaf(kb[u].w, d[j + 3], acc3);
            }
        }
    }

    // ---- shared row 7: tz=0 takes taps 0..7, tz=1 takes taps 8..14 ----
    {
        const float* row = &tile[(ty + 7) * SMEM_W + w];
        float d[20];
        #pragma unroll
        for (int v4 = 0; v4 < 5; v4++) {
            const float4 rv = *reinterpret_cast<const float4*>(row + v4 * 4);
            d[v4 * 4 + 0] = rv.x;
            d[v4 * 4 + 1] = rv.y;
            d[v4 * 4 + 2] = rv.z;
            d[v4 * 4 + 3] = rv.w;
        }
        const float* kp = kbase + (size_t)(7 * KSZ) * KSTRIDE;

        if (tz == 0) {
            #pragma unroll
            for (int u = 0; u < 8; u++)
                kv[u] = __ldcs(reinterpret_cast<const float4*>(
                    kp + (size_t)u * KSTRIDE));
            #pragma unroll
            for (int u = 0; u < 8; u++) {
                acc0 = fmaf(kv[u].x, d[u + 0], acc0);
                acc1 = fmaf(kv[u].y, d[u + 1], acc1);
                acc2 = fmaf(kv[u].z, d[u + 2], acc2);
                acc3 = fmaf(kv[u].w, d[u + 3], acc3);
            }
        } else {
            float4 kb[7];
            #pragma unroll
            for (int u = 0; u < 7; u++)
                kb[u] = __ldcs(reinterpret_cast<const float4*>(
                    kp + (size_t)(8 + u) * KSTRIDE));
            #pragma unroll
            for (int u = 0; u < 7; u++) {
                const int j = 8 + u;
                acc0 = fmaf(kb[u].x, d[j + 0], acc0);
                acc1 = fmaf(kb[u].y, d[j + 1], acc1);
                acc2 = fmaf(kb[u].z, d[j + 2], acc2);
                acc3 = fmaf(kb[u].w, d[j + 3], acc3);
            }
        }
    }

    // ---- cross-z reduction through shared memory ----
    if (tz == 1) {
        part[ty][tx][0] = acc0;
        part[ty][tx][1] = acc1;
        part[ty][tx][2] = acc2;
        part[ty][tx][3] = acc3;
    }
    __syncthreads();
    if (tz == 0) {
        acc0 += part[ty][tx][0];
        acc1 += part[ty][tx][1];
        acc2 += part[ty][tx][2];
        acc3 += part[ty][tx][3];
        *reinterpret_cast<float4*>(out + (size_t)tc * SLAB + (size_t)h * WW + w)
            = make_float4(acc0, acc1, acc2, acc3);
    }
}

extern "C" void kernel_launch(void* const* d_in, const int* in_sizes, int n_in,
                              void* d_out, int out_size)
{
    // data is the small tensor (221184), kernels the big one (49766400);
    // detect by size to be robust to metadata ordering.
    const float* data;
    const float* kernels;
    if (in_sizes[0] < in_sizes[1]) {
        data    = (const float*)d_in[0];
        kernels = (const float*)d_in[1];
    } else {
        data    = (const float*)d_in[1];
        kernels = (const float*)d_in[0];
    }

    dim3 grid(HH / TILE_H, TTT * CCH);      // (6, 24) = 144 blocks, 1/SM
    dim3 block(24, TILE_H, 2);              // (24, 16, 2) = 768 threads
    kpn_kernel<<<grid, block>>>(data, kernels, (float*)d_out);
}

// round 15
// speedup vs baseline: 1.5960x; 1.5960x over previous
#include <cuda_runtime.h>
#include <cstddef>

// KPN per-pixel dynamic convolution, K=15.
// data:    [1, 8, 3, 96, 96]      float32
// kernels: [1, 8, 225, 3, 96, 96] float32   (tap-major: k = i*15 + j)
// out:     [1, 8, 3, 96, 96]      float32
//
// R15 = R13 (champion, 33.25us) reverted from the failed L2-prefetch
// experiment (R14: 56us, prefetch traffic evicted before use -> double
// DRAM fetch). Single local tweak: output store via __stcs (write-once
// data, keep it out of L2). Shape: 768-thr blocks, 144 blocks = 1 CTA/SM,
// balanced 113/112 z-split, pipelined prologue, __ldcs stream loads.

#define KSZ    15
#define PAD    7
#define HH     96
#define WW     96
#define CCH    3
#define TTT    8
#define TILE_H 16
#define SMEM_W 112                 // 96 + 14 halo = 110 -> 112 (16B align)
#define SMEM_H (TILE_H + KSZ - 1)  // 30
#define SLAB   (HH * WW)           // 9216
#define KSTRIDE (CCH * HH * WW)    // 27648 floats between consecutive taps
#define NTHREADS (24 * TILE_H * 2) // 768
#define TILE_N  (SMEM_H * SMEM_W)  // 3360
#define NLOAD   ((TILE_N + NTHREADS - 1) / NTHREADS)  // 5

__global__ __launch_bounds__(NTHREADS, 1)
void kpn_kernel(const float* __restrict__ data,
                const float* __restrict__ kernels,
                float* __restrict__ out)
{
    __shared__ float tile[TILE_N];                 // 13440 B
    __shared__ float part[TILE_H][24][4];          //  6144 B

    const int tc = blockIdx.y;             // t*3 + c, 0..23
    const int h0 = blockIdx.x * TILE_H;    // output row base
    const float* dslab = data + (size_t)tc * SLAB;

    const int tx = threadIdx.x;            // 0..23  (w / 4)
    const int ty = threadIdx.y;            // 0..15  (row in tile)
    const int tz = threadIdx.z;            // 0..1   (tap-row group)
    const int tid = (tz * TILE_H + ty) * 24 + tx;   // 0..767

    const int w = tx * 4;                  // 0,4,...,92
    const int h = h0 + ty;
    const int t = tc / CCH;
    const int c = tc - t * CCH;

    // kernels[t, k, c, h, w] with k varying: base + k*KSTRIDE
    const float* kbase = kernels
        + ((size_t)(t * (KSZ * KSZ)) * CCH + c) * SLAB
        + (size_t)h * WW + w;

    const int i0 = tz * 8;                 // tz=0: rows 0..6(+7A); tz=1: rows 8..14(+7B)
    const float* kp0 = kbase + (size_t)(i0 * KSZ) * KSTRIDE;

    // ---- pipelined prologue ----
    // 1) tile gathers into registers (DRAM latency starts now)
    float tv[NLOAD];
    #pragma unroll
    for (int v = 0; v < NLOAD; v++) {
        const int idx = v * NTHREADS + tid;
        float val = 0.0f;
        if (idx < TILE_N) {
            const int r  = idx / SMEM_W;
            const int cc = idx - r * SMEM_W;
            const int gh = h0 - PAD + r;
            const int gw = cc - PAD;
            if ((unsigned)gh < (unsigned)HH && (unsigned)gw < (unsigned)WW)
                val = dslab[gh * WW + gw];
        }
        tv[v] = val;
    }
    // 2) first kv batch (independent of tile) — stream starts here
    float4 kv[8];
    #pragma unroll
    for (int u = 0; u < 8; u++)
        kv[u] = __ldcs(reinterpret_cast<const float4*>(
            kp0 + (size_t)u * KSTRIDE));
    // 3) tile stores + barrier (latency of 1+2 overlaps this wait)
    #pragma unroll
    for (int v = 0; v < NLOAD; v++) {
        const int idx = v * NTHREADS + tid;
        if (idx < TILE_N) tile[idx] = tv[v];
    }
    __syncthreads();

    float acc0 = 0.0f, acc1 = 0.0f, acc2 = 0.0f, acc3 = 0.0f;

    // ---- 7 full tap rows per z-half ----
    #pragma unroll
    for (int ii = 0; ii < 7; ii++) {
        const int i = i0 + ii;                   // tap row

        // data row segment: smem cols w .. w+19 (taps j=0..14 for 4 outputs)
        const float* row = &tile[(ty + i) * SMEM_W + w];
        float d[20];
        #pragma unroll
        for (int v4 = 0; v4 < 5; v4++) {
            const float4 rv = *reinterpret_cast<const float4*>(row + v4 * 4);
            d[v4 * 4 + 0] = rv.x;
            d[v4 * 4 + 1] = rv.y;
            d[v4 * 4 + 2] = rv.z;
            d[v4 * 4 + 3] = rv.w;
        }
        const float* kp = kbase + (size_t)(i * KSZ) * KSTRIDE;

        // batch A: taps 0..7 (prefetched to regs for ii==0)
        if (ii != 0) {
            #pragma unroll
            for (int u = 0; u < 8; u++)
                kv[u] = __ldcs(reinterpret_cast<const float4*>(
                    kp + (size_t)u * KSTRIDE));
        }
        #pragma unroll
        for (int u = 0; u < 8; u++) {
            acc0 = fmaf(kv[u].x, d[u + 0], acc0);
            acc1 = fmaf(kv[u].y, d[u + 1], acc1);
            acc2 = fmaf(kv[u].z, d[u + 2], acc2);
            acc3 = fmaf(kv[u].w, d[u + 3], acc3);
        }
        // batch B: taps 8..14
        {
            float4 kb[7];
            #pragma unroll
            for (int u = 0; u < 7; u++)
                kb[u] = __ldcs(reinterpret_cast<const float4*>(
                    kp + (size_t)(8 + u) * KSTRIDE));
            #pragma unroll
            for (int u = 0; u < 7; u++) {
                const int j = 8 + u;
                acc0 = fmaf(kb[u].x, d[j + 0], acc0);
                acc1 = fmaf(kb[u].y, d[j + 1], acc1);
                acc2 = fmaf(kb[u].z, d[j + 2], acc2);
                acc3 = fmaf(kb[u].w, d[j + 3], acc3);
            }
        }
    }

    // ---- shared row 7: tz=0 takes taps 0..7, tz=1 takes taps 8..14 ----
    {
        const float* row = &tile[(ty + 7) * SMEM_W + w];
        float d[20];
        #pragma unroll
        for (int v4 = 0; v4 < 5; v4++) {
            const float4 rv = *reinterpret_cast<const float4*>(row + v4 * 4);
            d[v4 * 4 + 0] = rv.x;
            d[v4 * 4 + 1] = rv.y;
            d[v4 * 4 + 2] = rv.z;
            d[v4 * 4 + 3] = rv.w;
        }
        const float* kp = kbase + (size_t)(7 * KSZ) * KSTRIDE;

        if (tz == 0) {
            #pragma unroll
            for (int u = 0; u < 8; u++)
                kv[u] = __ldcs(reinterpret_cast<const float4*>(
                    kp + (size_t)u * KSTRIDE));
            #pragma unroll
            for (int u = 0; u < 8; u++) {
                acc0 = fmaf(kv[u].x, d[u + 0], acc0);
                acc1 = fmaf(kv[u].y, d[u + 1], acc1);
                acc2 = fmaf(kv[u].z, d[u + 2], acc2);
                acc3 = fmaf(kv[u].w, d[u + 3], acc3);
            }
        } else {
            float4 kb[7];
            #pragma unroll
            for (int u = 0; u < 7; u++)
                kb[u] = __ldcs(reinterpret_cast<const float4*>(
                    kp + (size_t)(8 + u) * KSTRIDE));
            #pragma unroll
            for (int u = 0; u < 7; u++) {
                const int j = 8 + u;
                acc0 = fmaf(kb[u].x, d[j + 0], acc0);
                acc1 = fmaf(kb[u].y, d[j + 1], acc1);
                acc2 = fmaf(kb[u].z, d[j + 2], acc2);
                acc3 = fmaf(kb[u].w, d[j + 3], acc3);
            }
        }
    }

    // ---- cross-z reduction through shared memory ----
    if (tz == 1) {
        part[ty][tx][0] = acc0;
        part[ty][tx][1] = acc1;
        part[ty][tx][2] = acc2;
        part[ty][tx][3] = acc3;
    }
    __syncthreads();
    if (tz == 0) {
        acc0 += part[ty][tx][0];
        acc1 += part[ty][tx][1];
        acc2 += part[ty][tx][2];
        acc3 += part[ty][tx][3];
        // streaming store: output is write-once, keep it out of L2
        __stcs(reinterpret_cast<float4*>(
                   out + (size_t)tc * SLAB + (size_t)h * WW + w),
               make_float4(acc0, acc1, acc2, acc3));
    }
}

extern "C" void kernel_launch(void* const* d_in, const int* in_sizes, int n_in,
                              void* d_out, int out_size)
{
    // data is the small tensor (221184), kernels the big one (49766400);
    // detect by size to be robust to metadata ordering.
    const float* data;
    const float* kernels;
    if (in_sizes[0] < in_sizes[1]) {
        data    = (const float*)d_in[0];
        kernels = (const float*)d_in[1];
    } else {
        data    = (const float*)d_in[1];
        kernels = (const float*)d_in[0];
    }

    dim3 grid(HH / TILE_H, TTT * CCH);      // (6, 24) = 144 blocks, 1/SM
    dim3 block(24, TILE_H, 2);              // (24, 16, 2) = 768 threads
    kpn_kernel<<<grid, block>>>(data, kernels, (float*)d_out);
}

// round 16
// speedup vs baseline: 1.6959x; 1.0626x over previous
#include <cuda_runtime.h>
#include <cstddef>

// KPN per-pixel dynamic convolution, K=15.
// data:    [1, 8, 3, 96, 96]      float32
// kernels: [1, 8, 225, 3, 96, 96] float32   (tap-major: k = i*15 + j)
// out:     [1, 8, 3, 96, 96]      float32
//
// R16 = R13 restored byte-for-byte (champion, 33.25us). R15's __stcs
// "tweak" perturbed ptxas scheduling and cost 1.8us; plain STG.128 is the
// measured-best epilogue. Final configuration:
//   - 768-thr blocks (24,16,2), 144 blocks = 1 CTA/SM (no cross-CTA spread)
//   - balanced 113/112 tap split across tz (shared row 7 split A/B)
//   - pipelined prologue: tile->regs, first kv batch issued pre-barrier
//   - register-MLP 8 float4 __ldcs stream loads per batch
// Measured: 6.12 TB/s (77% of spec), ~5% above the practical HBM floor.

#define KSZ    15
#define PAD    7
#define HH     96
#define WW     96
#define CCH    3
#define TTT    8
#define TILE_H 16
#define SMEM_W 112                 // 96 + 14 halo = 110 -> 112 (16B align)
#define SMEM_H (TILE_H + KSZ - 1)  // 30
#define SLAB   (HH * WW)           // 9216
#define KSTRIDE (CCH * HH * WW)    // 27648 floats between consecutive taps
#define NTHREADS (24 * TILE_H * 2) // 768
#define TILE_N  (SMEM_H * SMEM_W)  // 3360
#define NLOAD   ((TILE_N + NTHREADS - 1) / NTHREADS)  // 5

__global__ __launch_bounds__(NTHREADS, 1)
void kpn_kernel(const float* __restrict__ data,
                const float* __restrict__ kernels,
                float* __restrict__ out)
{
    __shared__ float tile[TILE_N];                 // 13440 B
    __shared__ float part[TILE_H][24][4];          //  6144 B

    const int tc = blockIdx.y;             // t*3 + c, 0..23
    const int h0 = blockIdx.x * TILE_H;    // output row base
    const float* dslab = data + (size_t)tc * SLAB;

    const int tx = threadIdx.x;            // 0..23  (w / 4)
    const int ty = threadIdx.y;            // 0..15  (row in tile)
    const int tz = threadIdx.z;            // 0..1   (tap-row group)
    const int tid = (tz * TILE_H + ty) * 24 + tx;   // 0..767

    const int w = tx * 4;                  // 0,4,...,92
    const int h = h0 + ty;
    const int t = tc / CCH;
    const int c = tc - t * CCH;

    // kernels[t, k, c, h, w] with k varying: base + k*KSTRIDE
    const float* kbase = kernels
        + ((size_t)(t * (KSZ * KSZ)) * CCH + c) * SLAB
        + (size_t)h * WW + w;

    const int i0 = tz * 8;                 // tz=0: rows 0..6(+7A); tz=1: rows 8..14(+7B)
    const float* kp0 = kbase + (size_t)(i0 * KSZ) * KSTRIDE;

    // ---- pipelined prologue ----
    // 1) tile gathers into registers (DRAM latency starts now)
    float tv[NLOAD];
    #pragma unroll
    for (int v = 0; v < NLOAD; v++) {
        const int idx = v * NTHREADS + tid;
        float val = 0.0f;
        if (idx < TILE_N) {
            const int r  = idx / SMEM_W;
            const int cc = idx - r * SMEM_W;
            const int gh = h0 - PAD + r;
            const int gw = cc - PAD;
            if ((unsigned)gh < (unsigned)HH && (unsigned)gw < (unsigned)WW)
                val = dslab[gh * WW + gw];
        }
        tv[v] = val;
    }
    // 2) first kv batch (independent of tile) — stream starts here
    float4 kv[8];
    #pragma unroll
    for (int u = 0; u < 8; u++)
        kv[u] = __ldcs(reinterpret_cast<const float4*>(
            kp0 + (size_t)u * KSTRIDE));
    // 3) tile stores + barrier (latency of 1+2 overlaps this wait)
    #pragma unroll
    for (int v = 0; v < NLOAD; v++) {
        const int idx = v * NTHREADS + tid;
        if (idx < TILE_N) tile[idx] = tv[v];
    }
    __syncthreads();

    float acc0 = 0.0f, acc1 = 0.0f, acc2 = 0.0f, acc3 = 0.0f;

    // ---- 7 full tap rows per z-half ----
    #pragma unroll
    for (int ii = 0; ii < 7; ii++) {
        const int i = i0 + ii;                   // tap row

        // data row segment: smem cols w .. w+19 (taps j=0..14 for 4 outputs)
        const float* row = &tile[(ty + i) * SMEM_W + w];
        float d[20];
        #pragma unroll
        for (int v4 = 0; v4 < 5; v4++) {
            const float4 rv = *reinterpret_cast<const float4*>(row + v4 * 4);
            d[v4 * 4 + 0] = rv.x;
            d[v4 * 4 + 1] = rv.y;
            d[v4 * 4 + 2] = rv.z;
            d[v4 * 4 + 3] = rv.w;
        }
        const float* kp = kbase + (size_t)(i * KSZ) * KSTRIDE;

        // batch A: taps 0..7 (prefetched to regs for ii==0)
        if (ii != 0) {
            #pragma unroll
            for (int u = 0; u < 8; u++)
                kv[u] = __ldcs(reinterpret_cast<const float4*>(
                    kp + (size_t)u * KSTRIDE));
        }
        #pragma unroll
        for (int u = 0; u < 8; u++) {
            acc0 = fmaf(kv[u].x, d[u + 0], acc0);
            acc1 = fmaf(kv[u].y, d[u + 1], acc1);
            acc2 = fmaf(kv[u].z, d[u + 2], acc2);
            acc3 = fmaf(kv[u].w, d[u + 3], acc3);
        }
        // batch B: taps 8..14
        {
            float4 kb[7];
            #pragma unroll
            for (int u = 0; u < 7; u++)
                kb[u] = __ldcs(reinterpret_cast<const float4*>(
                    kp + (size_t)(8 + u) * KSTRIDE));
            #pragma unroll
            for (int u = 0; u < 7; u++) {
                const int j = 8 + u;
                acc0 = fmaf(kb[u].x, d[j + 0], acc0);
                acc1 = fmaf(kb[u].y, d[j + 1], acc1);
                acc2 = fmaf(kb[u].z, d[j + 2], acc2);
                acc3 = fmaf(kb[u].w, d[j + 3], acc3);
            }
        }
    }

    // ---- shared row 7: tz=0 takes taps 0..7, tz=1 takes taps 8..14 ----
    {
        const float* row = &tile[(ty + 7) * SMEM_W + w];
        float d[20];
        #pragma unroll
        for (int v4 = 0; v4 < 5; v4++) {
            const float4 rv = *reinterpret_cast<const float4*>(row + v4 * 4);
            d[v4 * 4 + 0] = rv.x;
            d[v4 * 4 + 1] = rv.y;
            d[v4 * 4 + 2] = rv.z;
            d[v4 * 4 + 3] = rv.w;
        }
        const float* kp = kbase + (size_t)(7 * KSZ) * KSTRIDE;

        if (tz == 0) {
            #pragma unroll
            for (int u = 0; u < 8; u++)
                kv[u] = __ldcs(reinterpret_cast<const float4*>(
                    kp + (size_t)u * KSTRIDE));
            #pragma unroll
            for (int u = 0; u < 8; u++) {
                acc0 = fmaf(kv[u].x, d[u + 0], acc0);
                acc1 = fmaf(kv[u].y, d[u + 1], acc1);
                acc2 = fmaf(kv[u].z, d[u + 2], acc2);
                acc3 = fmaf(kv[u].w, d[u + 3], acc3);
            }
        } else {
            float4 kb[7];
            #pragma unroll
            for (int u = 0; u < 7; u++)
                kb[u] = __ldcs(reinterpret_cast<const float4*>(
                    kp + (size_t)(8 + u) * KSTRIDE));
            #pragma unroll
            for (int u = 0; u < 7; u++) {
                const int j = 8 + u;
                acc0 = fmaf(kb[u].x, d[j + 0], acc0);
                acc1 = fmaf(kb[u].y, d[j + 1], acc1);
                acc2 = fmaf(kb[u].z, d[j + 2], acc2);
                acc3 = fmaf(kb[u].w, d[j + 3], acc3);
            }
        }
    }

    // ---- cross-z reduction through shared memory ----
    if (tz == 1) {
        part[ty][tx][0] = acc0;
        part[ty][tx][1] = acc1;
        part[ty][tx][2] = acc2;
        part[ty][tx][3] = acc3;
    }
    __syncthreads();
    if (tz == 0) {
        acc0 += part[ty][tx][0];
        acc1 += part[ty][tx][1];
        acc2 += part[ty][tx][2];
        acc3 += part[ty][tx][3];
        *reinterpret_cast<float4*>(out + (size_t)tc * SLAB + (size_t)h * WW + w)
            = make_float4(acc0, acc1, acc2, acc3);
    }
}

extern "C" void kernel_launch(void* const* d_in, const int* in_sizes, int n_in,
                              void* d_out, int out_size)
{
    // data is the small tensor (221184), kernels the big one (49766400);
    // detect by size to be robust to metadata ordering.
    const float* data;
    const float* kernels;
    if (in_sizes[0] < in_sizes[1]) {
        data    = (const float*)d_in[0];
        kernels = (const float*)d_in[1];
    } else {
        data    = (const float*)d_in[1];
        kernels = (const float*)d_in[0];
    }

    dim3 grid(HH / TILE_H, TTT * CCH);      // (6, 24) = 144 blocks, 1/SM
    dim3 block(24, TILE_H, 2);              // (24, 16, 2) = 768 threads
    kpn_kernel<<<grid, block>>>(data, kernels, (float*)d_out);
}